// round 1
// baseline (speedup 1.0000x reference)
#include <cuda_runtime.h>
#include <math.h>

// Problem constants: q,k,v : [B, S, D] float32
#define BATCH 8
#define SEQ   2048
#define DIM   512

// GEMM tiling
#define BM 128
#define BN 128
#define BKT 16
#define TM 8
#define TN 8
#define NT 256   // (BM/TM)*(BN/TN)

// ---------------------------------------------------------------------------
// Batched tiled fp32 GEMM.
//   C[b][m][n] = alpha * sum_k A[b][m][k] * B'[b][k][n]
// A is [M, Kd] row-major per batch.
// B_K_MAJOR = true : B operand is [N, Kd] row-major (B'[k][n] = B[n][k])  (Q·K^T)
// B_K_MAJOR = false: B operand is [Kd, N] row-major                      (W·V)
// ---------------------------------------------------------------------------
template <bool B_K_MAJOR>
__global__ __launch_bounds__(NT)
void gemm_kernel(const float* __restrict__ A,
                 const float* __restrict__ Bm,
                 float* __restrict__ C,
                 int M, int N, int Kd, float alpha)
{
    __shared__ float As[BKT][BM];
    __shared__ float Bs[BKT][BN];

    const int b = blockIdx.z;
    const float* Ab = A  + (size_t)b * (size_t)M * Kd;
    const float* Bb = Bm + (size_t)b * (B_K_MAJOR ? (size_t)N * Kd : (size_t)Kd * N);
    float*       Cb = C  + (size_t)b * (size_t)M * N;

    const int n0 = blockIdx.x * BN;
    const int m0 = blockIdx.y * BM;
    const int tid = threadIdx.x;
    const int tx = tid & 15;   // 0..15  -> 8 cols each
    const int ty = tid >> 4;   // 0..15  -> 8 rows each

    float acc[TM][TN];
#pragma unroll
    for (int i = 0; i < TM; i++)
#pragma unroll
        for (int j = 0; j < TN; j++)
            acc[i][j] = 0.0f;

    for (int k0 = 0; k0 < Kd; k0 += BKT) {
        // --- load A tile (BM x BKT), store transposed As[k][m] ---
#pragma unroll
        for (int l = 0; l < 2; l++) {
            int i = tid + l * NT;          // 0..511 over 512 float4 slots
            int m = i >> 2;                // 0..127
            int c = (i & 3) << 2;          // 0,4,8,12
            float4 v = *reinterpret_cast<const float4*>(
                Ab + (size_t)(m0 + m) * Kd + k0 + c);
            As[c + 0][m] = v.x;
            As[c + 1][m] = v.y;
            As[c + 2][m] = v.z;
            As[c + 3][m] = v.w;
        }
        // --- load B tile, store Bs[k][n] ---
        if (B_K_MAJOR) {
#pragma unroll
            for (int l = 0; l < 2; l++) {
                int i = tid + l * NT;
                int n = i >> 2;            // 0..127
                int c = (i & 3) << 2;      // 0,4,8,12
                float4 v = *reinterpret_cast<const float4*>(
                    Bb + (size_t)(n0 + n) * Kd + k0 + c);
                Bs[c + 0][n] = v.x;
                Bs[c + 1][n] = v.y;
                Bs[c + 2][n] = v.z;
                Bs[c + 3][n] = v.w;
            }
        } else {
#pragma unroll
            for (int l = 0; l < 2; l++) {
                int i = tid + l * NT;
                int kk = i >> 5;           // 0..15
                int c  = (i & 31) << 2;    // 0..124
                float4 v = *reinterpret_cast<const float4*>(
                    Bb + (size_t)(k0 + kk) * N + n0 + c);
                *reinterpret_cast<float4*>(&Bs[kk][c]) = v;
            }
        }
        __syncthreads();

        // --- compute ---
#pragma unroll
        for (int kk = 0; kk < BKT; kk++) {
            float a[TM], bb[TN];
            *reinterpret_cast<float4*>(&a[0]) =
                *reinterpret_cast<const float4*>(&As[kk][ty * TM]);
            *reinterpret_cast<float4*>(&a[4]) =
                *reinterpret_cast<const float4*>(&As[kk][ty * TM + 4]);
            *reinterpret_cast<float4*>(&bb[0]) =
                *reinterpret_cast<const float4*>(&Bs[kk][tx * TN]);
            *reinterpret_cast<float4*>(&bb[4]) =
                *reinterpret_cast<const float4*>(&Bs[kk][tx * TN + 4]);
#pragma unroll
            for (int i = 0; i < TM; i++)
#pragma unroll
                for (int j = 0; j < TN; j++)
                    acc[i][j] = fmaf(a[i], bb[j], acc[i][j]);
        }
        __syncthreads();
    }

    // --- store C (8x8 per thread, vectorized) ---
#pragma unroll
    for (int i = 0; i < TM; i++) {
        size_t off = (size_t)(m0 + ty * TM + i) * N + n0 + tx * TN;
        float4 o0, o1;
        o0.x = acc[i][0] * alpha; o0.y = acc[i][1] * alpha;
        o0.z = acc[i][2] * alpha; o0.w = acc[i][3] * alpha;
        o1.x = acc[i][4] * alpha; o1.y = acc[i][5] * alpha;
        o1.z = acc[i][6] * alpha; o1.w = acc[i][7] * alpha;
        *reinterpret_cast<float4*>(Cb + off)     = o0;
        *reinterpret_cast<float4*>(Cb + off + 4) = o1;
    }
}

// ---------------------------------------------------------------------------
// In-place row softmax over rows of length SEQ (2048). One CTA per row,
// 256 threads, 8 elements per thread held in registers.
// ---------------------------------------------------------------------------
__global__ __launch_bounds__(256)
void softmax_kernel(float* __restrict__ W)
{
    const size_t row = blockIdx.x;
    float* p = W + row * (size_t)SEQ;
    const int t = threadIdx.x;

    float4 v0 = reinterpret_cast<const float4*>(p)[t];
    float4 v1 = reinterpret_cast<const float4*>(p)[t + 256];

    float m = fmaxf(fmaxf(fmaxf(v0.x, v0.y), fmaxf(v0.z, v0.w)),
                    fmaxf(fmaxf(v1.x, v1.y), fmaxf(v1.z, v1.w)));

    __shared__ float red[8];
#pragma unroll
    for (int o = 16; o > 0; o >>= 1)
        m = fmaxf(m, __shfl_xor_sync(0xffffffffu, m, o));
    if ((t & 31) == 0) red[t >> 5] = m;
    __syncthreads();
    float rowmax = red[0];
#pragma unroll
    for (int i = 1; i < 8; i++) rowmax = fmaxf(rowmax, red[i]);
    __syncthreads();

    v0.x = __expf(v0.x - rowmax); v0.y = __expf(v0.y - rowmax);
    v0.z = __expf(v0.z - rowmax); v0.w = __expf(v0.w - rowmax);
    v1.x = __expf(v1.x - rowmax); v1.y = __expf(v1.y - rowmax);
    v1.z = __expf(v1.z - rowmax); v1.w = __expf(v1.w - rowmax);

    float s = ((v0.x + v0.y) + (v0.z + v0.w)) + ((v1.x + v1.y) + (v1.z + v1.w));
#pragma unroll
    for (int o = 16; o > 0; o >>= 1)
        s += __shfl_xor_sync(0xffffffffu, s, o);
    if ((t & 31) == 0) red[t >> 5] = s;
    __syncthreads();
    float rowsum = red[0];
#pragma unroll
    for (int i = 1; i < 8; i++) rowsum += red[i];

    const float inv = 1.0f / rowsum;
    v0.x *= inv; v0.y *= inv; v0.z *= inv; v0.w *= inv;
    v1.x *= inv; v1.y *= inv; v1.z *= inv; v1.w *= inv;

    reinterpret_cast<float4*>(p)[t]       = v0;
    reinterpret_cast<float4*>(p)[t + 256] = v1;
}

// ---------------------------------------------------------------------------
// Launch: out = [output (B*S*D) | attention_weights (B*S*S)]
// Weights region doubles as the scores scratch (no extra allocation).
// ---------------------------------------------------------------------------
extern "C" void kernel_launch(void* const* d_in, const int* in_sizes, int n_in,
                              void* d_out, int out_size)
{
    (void)in_sizes; (void)n_in; (void)out_size;
    const float* q = (const float*)d_in[0];
    const float* k = (const float*)d_in[1];
    const float* v = (const float*)d_in[2];
    float* out = (float*)d_out;
    float* w   = out + (size_t)BATCH * SEQ * DIM;   // weights / scores region

    const float inv_scale = 1.0f / sqrtf((float)SEQ);

    // 1) scores = Q K^T / sqrt(S)   (M=S, N=S, Kd=D)
    dim3 g1(SEQ / BN, SEQ / BM, BATCH);
    gemm_kernel<true><<<g1, NT>>>(q, k, w, SEQ, SEQ, DIM, inv_scale);

    // 2) softmax rows in place
    softmax_kernel<<<BATCH * SEQ, 256>>>(w);

    // 3) out = W V                  (M=S, N=D, Kd=S)
    dim3 g3(DIM / BN, SEQ / BM, BATCH);
    gemm_kernel<false><<<g3, NT>>>(w, v, out, SEQ, DIM, SEQ, 1.0f);
}

// round 3
// speedup vs baseline: 2.8120x; 2.8120x over previous
#include <cuda_runtime.h>
#include <cstdint>
#include <math.h>

// Problem constants: q,k,v : [B, S, D] float32
#define BATCH 8
#define SEQ   2048
#define DIM   512

// ---------------------------------------------------------------------------
// Scratch (__device__ globals; no allocation allowed)
// ---------------------------------------------------------------------------
__device__ float g_qr[(size_t)BATCH * SEQ * DIM];   // Q rounded to tf32
__device__ float g_kr[(size_t)BATCH * SEQ * DIM];   // K rounded to tf32
__device__ float g_vt[(size_t)BATCH * DIM * SEQ];   // V transposed (K-major) + rounded
__device__ float g_wr[(size_t)BATCH * SEQ * SEQ];   // weights rounded to tf32

__device__ __forceinline__ float tf32_rn(float x) {
    uint32_t u;
    asm("cvt.rna.tf32.f32 %0, %1;" : "=r"(u) : "f"(x));
    return __uint_as_float(u);
}

// ---------------------------------------------------------------------------
// tf32 warp-MMA GEMM:  C[b] = alpha * A[b] (MxK, K-major) * B[b]^T (NxK, K-major)
// CTA tile 128x128, BK=32, 4-stage cp.async pipeline, 8 warps (2x4),
// warp tile 64x32 built from m16n8k8 tf32 mma.sync.
// ---------------------------------------------------------------------------
#define BM 128
#define BN 128
#define BK 32
#define NST 4
#define LDS_STRIDE 36                       // floats; 36 mod 8 = 4 -> conflict-free frags
#define A_F (BM * LDS_STRIDE)               // 4608 floats
#define B_F (BN * LDS_STRIDE)               // 4608 floats
#define STAGE_F (A_F + B_F)                 // 9216 floats
#define GEMM_DSMEM (NST * STAGE_F * 4)      // 147456 bytes

__global__ __launch_bounds__(256, 1)
void gemm_mma(const float* __restrict__ A, const float* __restrict__ B,
              float* __restrict__ C, int M, int N, int Kd, float alpha)
{
    extern __shared__ float smem[];
    const uint32_t smem_b = (uint32_t)__cvta_generic_to_shared(smem);

    const int tid  = threadIdx.x;
    const int wid  = tid >> 5;
    const int lane = tid & 31;
    const int g    = lane >> 2;     // group 0..7
    const int tg   = lane & 3;      // 0..3

    const int wm = wid >> 2;        // 0..1  (M direction, 64 rows each)
    const int wn = wid & 3;         // 0..3  (N direction, 32 cols each)

    const int bz = blockIdx.z;
    const int n0 = blockIdx.x * BN;
    const int m0 = blockIdx.y * BM;
    const float* Ab = A + (size_t)bz * M * Kd;
    const float* Bb = B + (size_t)bz * N * Kd;
    float*       Cb = C + (size_t)bz * M * N;

    float acc[4][4][4];
#pragma unroll
    for (int i = 0; i < 4; i++)
#pragma unroll
        for (int j = 0; j < 4; j++)
#pragma unroll
            for (int r = 0; r < 4; r++)
                acc[i][j][r] = 0.0f;

    const int T = Kd / BK;

    // Each thread: row = tid>>3 (+32*r), chunk = tid&7 (16B each), 4 rows for A, 4 for B.
    const int lrow = tid >> 3;
    const int lch  = tid & 7;

    auto load_stage = [&](int buf, int kt) {
        const int k0 = kt * BK;
        const uint32_t ab = smem_b + (uint32_t)(buf * STAGE_F) * 4u;
        const uint32_t bb = ab + (uint32_t)A_F * 4u;
#pragma unroll
        for (int r = 0; r < 4; r++) {
            int row = lrow + r * 32;
            uint32_t d = ab + (uint32_t)(row * LDS_STRIDE + lch * 4) * 4u;
            const float* s = Ab + (size_t)(m0 + row) * Kd + k0 + lch * 4;
            asm volatile("cp.async.cg.shared.global [%0], [%1], 16;" :: "r"(d), "l"(s));
        }
#pragma unroll
        for (int r = 0; r < 4; r++) {
            int row = lrow + r * 32;
            uint32_t d = bb + (uint32_t)(row * LDS_STRIDE + lch * 4) * 4u;
            const float* s = Bb + (size_t)(n0 + row) * Kd + k0 + lch * 4;
            asm volatile("cp.async.cg.shared.global [%0], [%1], 16;" :: "r"(d), "l"(s));
        }
    };

    // Prefetch NST-1 stages
#pragma unroll
    for (int s = 0; s < NST - 1; s++) {
        load_stage(s, s);
        asm volatile("cp.async.commit_group;" ::: "memory");
    }

    for (int t = 0; t < T; t++) {
        asm volatile("cp.async.wait_group %0;" :: "n"(NST - 2) : "memory");
        __syncthreads();

        const int tn = t + NST - 1;
        if (tn < T) load_stage(tn & (NST - 1), tn);
        asm volatile("cp.async.commit_group;" ::: "memory");

        const int buf = t & (NST - 1);
        const float* As = smem + buf * STAGE_F;
        const float* Bs = As + A_F;
        const float* Aw = As + (wm * 64 + g) * LDS_STRIDE;          // + mt*16*stride
        const float* Bw = Bs + (wn * 32 + g) * LDS_STRIDE;          // + nt*8*stride

#pragma unroll
        for (int ks = 0; ks < BK / 8; ks++) {
            const int k8 = ks * 8;
            uint32_t a[4][4], b[4][2];
#pragma unroll
            for (int mt = 0; mt < 4; mt++) {
                const float* p = Aw + mt * 16 * LDS_STRIDE + k8 + tg;
                a[mt][0] = __float_as_uint(p[0]);
                a[mt][1] = __float_as_uint(p[8 * LDS_STRIDE]);
                a[mt][2] = __float_as_uint(p[4]);
                a[mt][3] = __float_as_uint(p[8 * LDS_STRIDE + 4]);
            }
#pragma unroll
            for (int nt = 0; nt < 4; nt++) {
                const float* p = Bw + nt * 8 * LDS_STRIDE + k8 + tg;
                b[nt][0] = __float_as_uint(p[0]);
                b[nt][1] = __float_as_uint(p[4]);
            }
#pragma unroll
            for (int mt = 0; mt < 4; mt++)
#pragma unroll
                for (int nt = 0; nt < 4; nt++) {
                    asm volatile(
                        "mma.sync.aligned.m16n8k8.row.col.f32.tf32.tf32.f32 "
                        "{%0,%1,%2,%3}, {%4,%5,%6,%7}, {%8,%9}, {%0,%1,%2,%3};"
                        : "+f"(acc[mt][nt][0]), "+f"(acc[mt][nt][1]),
                          "+f"(acc[mt][nt][2]), "+f"(acc[mt][nt][3])
                        : "r"(a[mt][0]), "r"(a[mt][1]), "r"(a[mt][2]), "r"(a[mt][3]),
                          "r"(b[nt][0]), "r"(b[nt][1]));
                }
        }
    }

    // Epilogue: c0=[g][2tg], c1=[g][2tg+1], c2=[g+8][2tg], c3=[g+8][2tg+1]
#pragma unroll
    for (int mt = 0; mt < 4; mt++) {
        const int row = m0 + wm * 64 + mt * 16 + g;
#pragma unroll
        for (int nt = 0; nt < 4; nt++) {
            const int col = n0 + wn * 32 + nt * 8 + 2 * tg;
            float2 lo, hi;
            lo.x = acc[mt][nt][0] * alpha; lo.y = acc[mt][nt][1] * alpha;
            hi.x = acc[mt][nt][2] * alpha; hi.y = acc[mt][nt][3] * alpha;
            *reinterpret_cast<float2*>(Cb + (size_t)row * N + col)       = lo;
            *reinterpret_cast<float2*>(Cb + (size_t)(row + 8) * N + col) = hi;
        }
    }
}

// ---------------------------------------------------------------------------
// Pre-pass: round fp32 -> nearest tf32
// ---------------------------------------------------------------------------
__global__ __launch_bounds__(256)
void round_tf32_kernel(const float4* __restrict__ in, float4* __restrict__ out, int n4)
{
    int i = blockIdx.x * blockDim.x + threadIdx.x;
    if (i < n4) {
        float4 v = in[i];
        v.x = tf32_rn(v.x); v.y = tf32_rn(v.y);
        v.z = tf32_rn(v.z); v.w = tf32_rn(v.w);
        out[i] = v;
    }
}

// ---------------------------------------------------------------------------
// Transpose V [B,S,D] -> Vt [B,D,S] with tf32 rounding (K-major B for GEMM2)
// ---------------------------------------------------------------------------
__global__ __launch_bounds__(256)
void transpose_round_kernel(const float* __restrict__ V, float* __restrict__ Vt)
{
    __shared__ float t[32][33];
    const int b = blockIdx.z;
    const float* Vb = V  + (size_t)b * SEQ * DIM;
    float*       Tb = Vt + (size_t)b * DIM * SEQ;
    const int s0 = blockIdx.x * 32;
    const int d0 = blockIdx.y * 32;
    const int x = threadIdx.x, y = threadIdx.y;   // 32 x 8
#pragma unroll
    for (int i = 0; i < 32; i += 8)
        t[y + i][x] = Vb[(size_t)(s0 + y + i) * DIM + d0 + x];
    __syncthreads();
#pragma unroll
    for (int i = 0; i < 32; i += 8)
        Tb[(size_t)(d0 + y + i) * SEQ + s0 + x] = tf32_rn(t[x][y + i]);
}

// ---------------------------------------------------------------------------
// Row softmax (len 2048, in place) + tf32-rounded copy to g_wr for GEMM2
// ---------------------------------------------------------------------------
__global__ __launch_bounds__(256)
void softmax_kernel(float* __restrict__ W, float* __restrict__ Wr)
{
    const size_t row = blockIdx.x;
    float* p  = W  + row * (size_t)SEQ;
    float* pr = Wr + row * (size_t)SEQ;
    const int t = threadIdx.x;

    float4 v0 = reinterpret_cast<const float4*>(p)[t];
    float4 v1 = reinterpret_cast<const float4*>(p)[t + 256];

    float m = fmaxf(fmaxf(fmaxf(v0.x, v0.y), fmaxf(v0.z, v0.w)),
                    fmaxf(fmaxf(v1.x, v1.y), fmaxf(v1.z, v1.w)));

    __shared__ float red[8];
#pragma unroll
    for (int o = 16; o > 0; o >>= 1)
        m = fmaxf(m, __shfl_xor_sync(0xffffffffu, m, o));
    if ((t & 31) == 0) red[t >> 5] = m;
    __syncthreads();
    float rowmax = red[0];
#pragma unroll
    for (int i = 1; i < 8; i++) rowmax = fmaxf(rowmax, red[i]);
    __syncthreads();

    v0.x = __expf(v0.x - rowmax); v0.y = __expf(v0.y - rowmax);
    v0.z = __expf(v0.z - rowmax); v0.w = __expf(v0.w - rowmax);
    v1.x = __expf(v1.x - rowmax); v1.y = __expf(v1.y - rowmax);
    v1.z = __expf(v1.z - rowmax); v1.w = __expf(v1.w - rowmax);

    float s = ((v0.x + v0.y) + (v0.z + v0.w)) + ((v1.x + v1.y) + (v1.z + v1.w));
#pragma unroll
    for (int o = 16; o > 0; o >>= 1)
        s += __shfl_xor_sync(0xffffffffu, s, o);
    if ((t & 31) == 0) red[t >> 5] = s;
    __syncthreads();
    float rowsum = red[0];
#pragma unroll
    for (int i = 1; i < 8; i++) rowsum += red[i];

    const float inv = 1.0f / rowsum;
    v0.x *= inv; v0.y *= inv; v0.z *= inv; v0.w *= inv;
    v1.x *= inv; v1.y *= inv; v1.z *= inv; v1.w *= inv;

    reinterpret_cast<float4*>(p)[t]       = v0;
    reinterpret_cast<float4*>(p)[t + 256] = v1;

    float4 r0, r1;
    r0.x = tf32_rn(v0.x); r0.y = tf32_rn(v0.y); r0.z = tf32_rn(v0.z); r0.w = tf32_rn(v0.w);
    r1.x = tf32_rn(v1.x); r1.y = tf32_rn(v1.y); r1.z = tf32_rn(v1.z); r1.w = tf32_rn(v1.w);
    reinterpret_cast<float4*>(pr)[t]       = r0;
    reinterpret_cast<float4*>(pr)[t + 256] = r1;
}

// ---------------------------------------------------------------------------
// Launch: out = [output (B*S*D) | attention_weights (B*S*S)]
// ---------------------------------------------------------------------------
extern "C" void kernel_launch(void* const* d_in, const int* in_sizes, int n_in,
                              void* d_out, int out_size)
{
    (void)in_sizes; (void)n_in; (void)out_size;
    const float* q = (const float*)d_in[0];
    const float* k = (const float*)d_in[1];
    const float* v = (const float*)d_in[2];
    float* out = (float*)d_out;
    float* w   = out + (size_t)BATCH * SEQ * DIM;   // weights / scores region

    float *qr, *kr, *vt, *wr;
    cudaGetSymbolAddress((void**)&qr, g_qr);
    cudaGetSymbolAddress((void**)&kr, g_kr);
    cudaGetSymbolAddress((void**)&vt, g_vt);
    cudaGetSymbolAddress((void**)&wr, g_wr);

    cudaFuncSetAttribute(gemm_mma, cudaFuncAttributeMaxDynamicSharedMemorySize, GEMM_DSMEM);

    const float inv_scale = 1.0f / sqrtf((float)SEQ);
    const int n4 = BATCH * SEQ * DIM / 4;

    // 1) round Q, K to tf32
    round_tf32_kernel<<<(n4 + 255) / 256, 256>>>((const float4*)q, (float4*)qr, n4);
    round_tf32_kernel<<<(n4 + 255) / 256, 256>>>((const float4*)k, (float4*)kr, n4);

    // 2) transpose + round V -> Vt [B, D, S]
    dim3 tg(SEQ / 32, DIM / 32, BATCH);
    transpose_round_kernel<<<tg, dim3(32, 8)>>>(v, vt);

    // 3) scores = Q K^T / sqrt(S)  (M=S, N=S, K=D; both K-major)
    dim3 g1(SEQ / BN, SEQ / BM, BATCH);
    gemm_mma<<<g1, 256, GEMM_DSMEM>>>(qr, kr, w, SEQ, SEQ, DIM, inv_scale);

    // 4) softmax rows in place; rounded copy to wr
    softmax_kernel<<<BATCH * SEQ, 256>>>(w, wr);

    // 5) out = W V  (M=S, N=D, K=S; A=wr K-major, B=Vt K-major)
    dim3 g2(DIM / BN, SEQ / BM, BATCH);
    gemm_mma<<<g2, 256, GEMM_DSMEM>>>(wr, vt, out, SEQ, DIM, SEQ, 1.0f);
}

// round 4
// speedup vs baseline: 5.0694x; 1.8028x over previous
#include <cuda_runtime.h>
#include <cuda_fp16.h>
#include <cstdint>
#include <math.h>

// Problem constants: q,k,v : [B, S, D] float32
#define BATCH 8
#define SEQ   2048
#define DIM   512

// ---------------------------------------------------------------------------
// Scratch (__device__ globals; no allocation allowed)
// ---------------------------------------------------------------------------
__device__ __half g_qh[(size_t)BATCH * SEQ * DIM];   // Q in fp16
__device__ __half g_kh[(size_t)BATCH * SEQ * DIM];   // K in fp16
__device__ __half g_vt[(size_t)BATCH * DIM * SEQ];   // V transposed (K-major), fp16
__device__ __half g_wh[(size_t)BATCH * SEQ * SEQ];   // softmax weights, fp16

// ---------------------------------------------------------------------------
// fp16 warp-MMA GEMM:  C[b] = alpha * A[b] (MxK, K-major) * B[b]^T (NxK, K-major)
// CTA tile 128x128, BK=64 halves (128B rows, XOR-swizzled), 4-stage cp.async,
// 8 warps (2x4), warp tile 64x32 from m16n8k16 f16 mma + ldmatrix.x4.
// ---------------------------------------------------------------------------
#define BM 128
#define BN 128
#define BKH 64                              // halves per stage-row (128 bytes)
#define NSTG 4
#define AB_BYTES (128 * 128)                // 128 rows x 128B = 16384
#define STAGE_BYTES (2 * AB_BYTES)          // 32768
#define HGEMM_DSMEM (NSTG * STAGE_BYTES)    // 131072

__device__ __forceinline__ void ldsm_x4(uint32_t r[4], uint32_t addr) {
    asm volatile("ldmatrix.sync.aligned.m8n8.x4.shared.b16 {%0,%1,%2,%3}, [%4];"
                 : "=r"(r[0]), "=r"(r[1]), "=r"(r[2]), "=r"(r[3]) : "r"(addr));
}

__global__ __launch_bounds__(256, 1)
void gemm_h(const __half* __restrict__ A, const __half* __restrict__ B,
            float* __restrict__ C, int M, int N, int Kd, float alpha)
{
    extern __shared__ char smem[];
    const uint32_t smem_b = (uint32_t)__cvta_generic_to_shared(smem);

    const int tid  = threadIdx.x;
    const int wid  = tid >> 5;
    const int lane = tid & 31;
    const int g    = lane >> 2;
    const int tg   = lane & 3;
    const int lr   = lane & 15;     // ldmatrix row-within-16
    const int lc   = lane >> 4;     // ldmatrix chunk select (0/1)

    const int wm = wid >> 2;        // 0..1 (64 rows each)
    const int wn = wid & 3;         // 0..3 (32 cols each)

    const int bz = blockIdx.z;
    const int n0 = blockIdx.x * BN;
    const int m0 = blockIdx.y * BM;
    const __half* Ab = A + (size_t)bz * M * Kd;
    const __half* Bb = B + (size_t)bz * N * Kd;
    float*        Cb = C + (size_t)bz * M * N;

    float acc[4][4][4];
#pragma unroll
    for (int i = 0; i < 4; i++)
#pragma unroll
        for (int j = 0; j < 4; j++)
#pragma unroll
            for (int r = 0; r < 4; r++)
                acc[i][j][r] = 0.0f;

    const int T = Kd / BKH;

    auto load_stage = [&](int buf, int kt) {
        const int k0 = kt * BKH;
        const uint32_t ab = smem_b + (uint32_t)buf * STAGE_BYTES;
        const uint32_t bb = ab + AB_BYTES;
#pragma unroll
        for (int i = 0; i < 4; i++) {              // A: 1024 16B chunks
            int idx = tid + i * 256;
            int row = idx >> 3;
            int c   = idx & 7;
            uint32_t d = ab + (uint32_t)(row * 128 + ((c ^ (row & 7)) << 4));
            const __half* s = Ab + (size_t)(m0 + row) * Kd + k0 + c * 8;
            asm volatile("cp.async.cg.shared.global [%0], [%1], 16;" :: "r"(d), "l"(s));
        }
#pragma unroll
        for (int i = 0; i < 4; i++) {              // B: 1024 16B chunks
            int idx = tid + i * 256;
            int row = idx >> 3;
            int c   = idx & 7;
            uint32_t d = bb + (uint32_t)(row * 128 + ((c ^ (row & 7)) << 4));
            const __half* s = Bb + (size_t)(n0 + row) * Kd + k0 + c * 8;
            asm volatile("cp.async.cg.shared.global [%0], [%1], 16;" :: "r"(d), "l"(s));
        }
    };

#pragma unroll
    for (int s = 0; s < NSTG - 1; s++) {
        load_stage(s, s);
        asm volatile("cp.async.commit_group;" ::: "memory");
    }

    for (int t = 0; t < T; t++) {
        asm volatile("cp.async.wait_group %0;" :: "n"(NSTG - 2) : "memory");
        __syncthreads();

        const int tn = t + NSTG - 1;
        if (tn < T) load_stage(tn & (NSTG - 1), tn);
        asm volatile("cp.async.commit_group;" ::: "memory");

        const int buf = t & (NSTG - 1);
        const uint32_t ab = smem_b + (uint32_t)buf * STAGE_BYTES;
        const uint32_t bb = ab + AB_BYTES;

#pragma unroll
        for (int ks = 0; ks < BKH / 16; ks++) {    // 4 k16 steps
            const int c = ks * 2 + lc;
            uint32_t a[4][4], b[2][4];
#pragma unroll
            for (int mt = 0; mt < 4; mt++) {
                int r = wm * 64 + mt * 16 + lr;
                ldsm_x4(a[mt], ab + (uint32_t)(r * 128 + ((c ^ (r & 7)) << 4)));
            }
#pragma unroll
            for (int pr = 0; pr < 2; pr++) {
                int r = wn * 32 + pr * 16 + lr;
                ldsm_x4(b[pr], bb + (uint32_t)(r * 128 + ((c ^ (r & 7)) << 4)));
            }
#pragma unroll
            for (int mt = 0; mt < 4; mt++)
#pragma unroll
                for (int nt = 0; nt < 4; nt++) {
                    const int pr = nt >> 1, od = nt & 1;
                    asm volatile(
                        "mma.sync.aligned.m16n8k16.row.col.f32.f16.f16.f32 "
                        "{%0,%1,%2,%3}, {%4,%5,%6,%7}, {%8,%9}, {%0,%1,%2,%3};"
                        : "+f"(acc[mt][nt][0]), "+f"(acc[mt][nt][1]),
                          "+f"(acc[mt][nt][2]), "+f"(acc[mt][nt][3])
                        : "r"(a[mt][0]), "r"(a[mt][1]), "r"(a[mt][2]), "r"(a[mt][3]),
                          "r"(b[pr][od]), "r"(b[pr][od + 2]));
                }
        }
    }

    // Epilogue: c0=[g][2tg], c1=[g][2tg+1], c2=[g+8][2tg], c3=[g+8][2tg+1]
#pragma unroll
    for (int mt = 0; mt < 4; mt++) {
        const int row = m0 + wm * 64 + mt * 16 + g;
#pragma unroll
        for (int nt = 0; nt < 4; nt++) {
            const int col = n0 + wn * 32 + nt * 8 + 2 * tg;
            float2 lo, hi;
            lo.x = acc[mt][nt][0] * alpha; lo.y = acc[mt][nt][1] * alpha;
            hi.x = acc[mt][nt][2] * alpha; hi.y = acc[mt][nt][3] * alpha;
            *reinterpret_cast<float2*>(Cb + (size_t)row * N + col)       = lo;
            *reinterpret_cast<float2*>(Cb + (size_t)(row + 8) * N + col) = hi;
        }
    }
}

// ---------------------------------------------------------------------------
// Pre-pass: fp32 -> fp16
// ---------------------------------------------------------------------------
__global__ __launch_bounds__(256)
void to_half_kernel(const float4* __restrict__ in, __half2* __restrict__ out, int n4)
{
    int i = blockIdx.x * blockDim.x + threadIdx.x;
    if (i < n4) {
        float4 v = in[i];
        out[2 * i]     = __float22half2_rn(make_float2(v.x, v.y));
        out[2 * i + 1] = __float22half2_rn(make_float2(v.z, v.w));
    }
}

// ---------------------------------------------------------------------------
// Transpose V [B,S,D] -> Vt [B,D,S] fp16 (K-major B operand for GEMM2)
// ---------------------------------------------------------------------------
__global__ __launch_bounds__(256)
void transpose_half_kernel(const float* __restrict__ V, __half* __restrict__ Vt)
{
    __shared__ float t[32][33];
    const int b = blockIdx.z;
    const float* Vb = V  + (size_t)b * SEQ * DIM;
    __half*      Tb = Vt + (size_t)b * DIM * SEQ;
    const int s0 = blockIdx.x * 32;
    const int d0 = blockIdx.y * 32;
    const int x = threadIdx.x, y = threadIdx.y;   // 32 x 8
#pragma unroll
    for (int i = 0; i < 32; i += 8)
        t[y + i][x] = Vb[(size_t)(s0 + y + i) * DIM + d0 + x];
    __syncthreads();
#pragma unroll
    for (int i = 0; i < 32; i += 8)
        Tb[(size_t)(d0 + y + i) * SEQ + s0 + x] = __float2half_rn(t[x][y + i]);
}

// ---------------------------------------------------------------------------
// Row softmax (len 2048, in place, fp32) + fp16 copy for GEMM2's A operand
// ---------------------------------------------------------------------------
__global__ __launch_bounds__(256)
void softmax_kernel(float* __restrict__ W, __half* __restrict__ Wh)
{
    const size_t row = blockIdx.x;
    float*  p  = W  + row * (size_t)SEQ;
    __half2* ph = reinterpret_cast<__half2*>(Wh + row * (size_t)SEQ);
    const int t = threadIdx.x;

    float4 v0 = reinterpret_cast<const float4*>(p)[t];
    float4 v1 = reinterpret_cast<const float4*>(p)[t + 256];

    float m = fmaxf(fmaxf(fmaxf(v0.x, v0.y), fmaxf(v0.z, v0.w)),
                    fmaxf(fmaxf(v1.x, v1.y), fmaxf(v1.z, v1.w)));

    __shared__ float red[8];
#pragma unroll
    for (int o = 16; o > 0; o >>= 1)
        m = fmaxf(m, __shfl_xor_sync(0xffffffffu, m, o));
    if ((t & 31) == 0) red[t >> 5] = m;
    __syncthreads();
    float rowmax = red[0];
#pragma unroll
    for (int i = 1; i < 8; i++) rowmax = fmaxf(rowmax, red[i]);
    __syncthreads();

    v0.x = __expf(v0.x - rowmax); v0.y = __expf(v0.y - rowmax);
    v0.z = __expf(v0.z - rowmax); v0.w = __expf(v0.w - rowmax);
    v1.x = __expf(v1.x - rowmax); v1.y = __expf(v1.y - rowmax);
    v1.z = __expf(v1.z - rowmax); v1.w = __expf(v1.w - rowmax);

    float s = ((v0.x + v0.y) + (v0.z + v0.w)) + ((v1.x + v1.y) + (v1.z + v1.w));
#pragma unroll
    for (int o = 16; o > 0; o >>= 1)
        s += __shfl_xor_sync(0xffffffffu, s, o);
    if ((t & 31) == 0) red[t >> 5] = s;
    __syncthreads();
    float rowsum = red[0];
#pragma unroll
    for (int i = 1; i < 8; i++) rowsum += red[i];

    const float inv = 1.0f / rowsum;
    v0.x *= inv; v0.y *= inv; v0.z *= inv; v0.w *= inv;
    v1.x *= inv; v1.y *= inv; v1.z *= inv; v1.w *= inv;

    reinterpret_cast<float4*>(p)[t]       = v0;
    reinterpret_cast<float4*>(p)[t + 256] = v1;

    ph[2 * t]           = __float22half2_rn(make_float2(v0.x, v0.y));
    ph[2 * t + 1]       = __float22half2_rn(make_float2(v0.z, v0.w));
    ph[512 + 2 * t]     = __float22half2_rn(make_float2(v1.x, v1.y));
    ph[512 + 2 * t + 1] = __float22half2_rn(make_float2(v1.z, v1.w));
}

// ---------------------------------------------------------------------------
// Launch: out = [output (B*S*D) | attention_weights (B*S*S)]
// ---------------------------------------------------------------------------
extern "C" void kernel_launch(void* const* d_in, const int* in_sizes, int n_in,
                              void* d_out, int out_size)
{
    (void)in_sizes; (void)n_in; (void)out_size;
    const float* q = (const float*)d_in[0];
    const float* k = (const float*)d_in[1];
    const float* v = (const float*)d_in[2];
    float* out = (float*)d_out;
    float* w   = out + (size_t)BATCH * SEQ * DIM;   // weights / scores region

    __half *qh, *kh, *vt, *wh;
    cudaGetSymbolAddress((void**)&qh, g_qh);
    cudaGetSymbolAddress((void**)&kh, g_kh);
    cudaGetSymbolAddress((void**)&vt, g_vt);
    cudaGetSymbolAddress((void**)&wh, g_wh);

    cudaFuncSetAttribute(gemm_h, cudaFuncAttributeMaxDynamicSharedMemorySize, HGEMM_DSMEM);

    const float inv_scale = 1.0f / sqrtf((float)SEQ);
    const int n4 = BATCH * SEQ * DIM / 4;

    // 1) convert Q, K to fp16
    to_half_kernel<<<(n4 + 255) / 256, 256>>>((const float4*)q, (__half2*)qh, n4);
    to_half_kernel<<<(n4 + 255) / 256, 256>>>((const float4*)k, (__half2*)kh, n4);

    // 2) transpose V -> Vt [B, D, S] fp16
    dim3 tg(SEQ / 32, DIM / 32, BATCH);
    transpose_half_kernel<<<tg, dim3(32, 8)>>>(v, vt);

    // 3) scores = Q K^T / sqrt(S)  (M=S, N=S, K=D)
    dim3 g1(SEQ / BN, SEQ / BM, BATCH);
    gemm_h<<<g1, 256, HGEMM_DSMEM>>>(qh, kh, w, SEQ, SEQ, DIM, inv_scale);

    // 4) softmax rows in place; fp16 copy to wh
    softmax_kernel<<<BATCH * SEQ, 256>>>(w, wh);

    // 5) out = W V  (M=S, N=D, K=S)
    dim3 g2(DIM / BN, SEQ / BM, BATCH);
    gemm_h<<<g2, 256, HGEMM_DSMEM>>>(wh, vt, out, SEQ, DIM, SEQ, 1.0f);
}

// round 5
// speedup vs baseline: 5.4388x; 1.0729x over previous
#include <cuda_runtime.h>
#include <cuda_fp16.h>
#include <cstdint>
#include <math.h>

// Problem constants: q,k,v : [B, S, D] float32
#define BATCH 8
#define SEQ   2048
#define DIM   512

// ---------------------------------------------------------------------------
// Scratch (__device__ globals; no allocation allowed)
// ---------------------------------------------------------------------------
__device__ __half g_qh[(size_t)BATCH * SEQ * DIM];   // Q in fp16
__device__ __half g_kh[(size_t)BATCH * SEQ * DIM];   // K in fp16
__device__ __half g_vt[(size_t)BATCH * DIM * SEQ];   // V transposed (K-major), fp16
__device__ __half g_wh[(size_t)BATCH * SEQ * SEQ];   // softmax weights, fp16

// ---------------------------------------------------------------------------
// fp16 warp-MMA GEMM:  C[b] = alpha * A[b] (MxK, K-major) * B[b]^T (NxK, K-major)
// CTA tile 128x256, BK=64 halves (128B rows, XOR-swizzled), 3-stage cp.async,
// 8 warps (2 in M x 4 in N), warp tile 64x64 from m16n8k16 + ldmatrix.x4.
// ---------------------------------------------------------------------------
#define BM 128
#define BN 256
#define BKH 64                               // halves per row-stage (128 bytes)
#define NSTG 3
#define A_BYTES (BM * 128)                   // 16384
#define B_BYTES (BN * 128)                   // 32768
#define STAGE_BYTES (A_BYTES + B_BYTES)      // 49152
#define HGEMM_DSMEM (NSTG * STAGE_BYTES)     // 147456

__device__ __forceinline__ void ldsm_x4(uint32_t r[4], uint32_t addr) {
    asm volatile("ldmatrix.sync.aligned.m8n8.x4.shared.b16 {%0,%1,%2,%3}, [%4];"
                 : "=r"(r[0]), "=r"(r[1]), "=r"(r[2]), "=r"(r[3]) : "r"(addr));
}

__global__ __launch_bounds__(256, 1)
void gemm_h(const __half* __restrict__ A, const __half* __restrict__ B,
            float* __restrict__ C, int M, int N, int Kd, float alpha)
{
    extern __shared__ char smem[];
    const uint32_t smem_b = (uint32_t)__cvta_generic_to_shared(smem);

    const int tid  = threadIdx.x;
    const int wid  = tid >> 5;
    const int lane = tid & 31;
    const int g    = lane >> 2;
    const int tg   = lane & 3;
    const int lr   = lane & 15;     // ldmatrix row-within-16
    const int lc   = lane >> 4;     // ldmatrix 16B-chunk select (0/1)

    const int wm = wid & 1;         // 0..1 (64 rows each)
    const int wn = wid >> 1;        // 0..3 (64 cols each)

    const int bz = blockIdx.z;
    const int n0 = blockIdx.x * BN;
    const int m0 = blockIdx.y * BM;
    const __half* Ab = A + (size_t)bz * M * Kd;
    const __half* Bb = B + (size_t)bz * N * Kd;
    float*        Cb = C + (size_t)bz * M * N;

    float acc[4][8][4];
#pragma unroll
    for (int i = 0; i < 4; i++)
#pragma unroll
        for (int j = 0; j < 8; j++)
#pragma unroll
            for (int r = 0; r < 4; r++)
                acc[i][j][r] = 0.0f;

    const int T = Kd / BKH;

    auto load_stage = [&](int buf, int kt) {
        const int k0 = kt * BKH;
        const uint32_t ab = smem_b + (uint32_t)buf * STAGE_BYTES;
        const uint32_t bb = ab + A_BYTES;
#pragma unroll
        for (int i = 0; i < 4; i++) {              // A: 1024 16B chunks
            int idx = tid + i * 256;
            int row = idx >> 3;
            int c   = idx & 7;
            uint32_t d = ab + (uint32_t)(row * 128 + ((c ^ (row & 7)) << 4));
            const __half* s = Ab + (size_t)(m0 + row) * Kd + k0 + c * 8;
            asm volatile("cp.async.cg.shared.global [%0], [%1], 16;" :: "r"(d), "l"(s));
        }
#pragma unroll
        for (int i = 0; i < 8; i++) {              // B: 2048 16B chunks
            int idx = tid + i * 256;
            int row = idx >> 3;
            int c   = idx & 7;
            uint32_t d = bb + (uint32_t)(row * 128 + ((c ^ (row & 7)) << 4));
            const __half* s = Bb + (size_t)(n0 + row) * Kd + k0 + c * 8;
            asm volatile("cp.async.cg.shared.global [%0], [%1], 16;" :: "r"(d), "l"(s));
        }
    };

#pragma unroll
    for (int s = 0; s < NSTG - 1; s++) {
        load_stage(s, s);
        asm volatile("cp.async.commit_group;" ::: "memory");
    }

    int cbuf = 0;            // compute buffer
    int lbuf = NSTG - 1;     // next load buffer
    for (int t = 0; t < T; t++) {
        asm volatile("cp.async.wait_group %0;" :: "n"(NSTG - 2) : "memory");
        __syncthreads();

        const int tn = t + NSTG - 1;
        if (tn < T) load_stage(lbuf, tn);
        asm volatile("cp.async.commit_group;" ::: "memory");
        lbuf = (lbuf + 1 == NSTG) ? 0 : lbuf + 1;

        const uint32_t ab = smem_b + (uint32_t)cbuf * STAGE_BYTES;
        const uint32_t bb = ab + A_BYTES;
        cbuf = (cbuf + 1 == NSTG) ? 0 : cbuf + 1;

#pragma unroll
        for (int ks = 0; ks < BKH / 16; ks++) {    // 4 k16 steps
            const int c = ks * 2 + lc;
            uint32_t a[4][4], b[4][4];
#pragma unroll
            for (int mt = 0; mt < 4; mt++) {
                int r = wm * 64 + mt * 16 + lr;
                ldsm_x4(a[mt], ab + (uint32_t)(r * 128 + ((c ^ (r & 7)) << 4)));
            }
#pragma unroll
            for (int pr = 0; pr < 4; pr++) {
                int r = wn * 64 + pr * 16 + lr;
                ldsm_x4(b[pr], bb + (uint32_t)(r * 128 + ((c ^ (r & 7)) << 4)));
            }
#pragma unroll
            for (int mt = 0; mt < 4; mt++)
#pragma unroll
                for (int nt = 0; nt < 8; nt++) {
                    const int pr = nt >> 1, od = nt & 1;
                    asm volatile(
                        "mma.sync.aligned.m16n8k16.row.col.f32.f16.f16.f32 "
                        "{%0,%1,%2,%3}, {%4,%5,%6,%7}, {%8,%9}, {%0,%1,%2,%3};"
                        : "+f"(acc[mt][nt][0]), "+f"(acc[mt][nt][1]),
                          "+f"(acc[mt][nt][2]), "+f"(acc[mt][nt][3])
                        : "r"(a[mt][0]), "r"(a[mt][1]), "r"(a[mt][2]), "r"(a[mt][3]),
                          "r"(b[pr][od]), "r"(b[pr][od + 2]));
                }
        }
    }

    // Epilogue: c0=[g][2tg], c1=[g][2tg+1], c2=[g+8][2tg], c3=[g+8][2tg+1]
#pragma unroll
    for (int mt = 0; mt < 4; mt++) {
        const int row = m0 + wm * 64 + mt * 16 + g;
#pragma unroll
        for (int nt = 0; nt < 8; nt++) {
            const int col = n0 + wn * 64 + nt * 8 + 2 * tg;
            float2 lo, hi;
            lo.x = acc[mt][nt][0] * alpha; lo.y = acc[mt][nt][1] * alpha;
            hi.x = acc[mt][nt][2] * alpha; hi.y = acc[mt][nt][3] * alpha;
            *reinterpret_cast<float2*>(Cb + (size_t)row * N + col)       = lo;
            *reinterpret_cast<float2*>(Cb + (size_t)(row + 8) * N + col) = hi;
        }
    }
}

// ---------------------------------------------------------------------------
// Pre-pass: fp32 -> fp16
// ---------------------------------------------------------------------------
__global__ __launch_bounds__(256)
void to_half_kernel(const float4* __restrict__ in, __half2* __restrict__ out, int n4)
{
    int i = blockIdx.x * blockDim.x + threadIdx.x;
    if (i < n4) {
        float4 v = in[i];
        out[2 * i]     = __float22half2_rn(make_float2(v.x, v.y));
        out[2 * i + 1] = __float22half2_rn(make_float2(v.z, v.w));
    }
}

// ---------------------------------------------------------------------------
// Transpose V [B,S,D] -> Vt [B,D,S] fp16 (K-major B operand for GEMM2)
// ---------------------------------------------------------------------------
__global__ __launch_bounds__(256)
void transpose_half_kernel(const float* __restrict__ V, __half* __restrict__ Vt)
{
    __shared__ float t[32][33];
    const int b = blockIdx.z;
    const float* Vb = V  + (size_t)b * SEQ * DIM;
    __half*      Tb = Vt + (size_t)b * DIM * SEQ;
    const int s0 = blockIdx.x * 32;
    const int d0 = blockIdx.y * 32;
    const int x = threadIdx.x, y = threadIdx.y;   // 32 x 8
#pragma unroll
    for (int i = 0; i < 32; i += 8)
        t[y + i][x] = Vb[(size_t)(s0 + y + i) * DIM + d0 + x];
    __syncthreads();
#pragma unroll
    for (int i = 0; i < 32; i += 8)
        Tb[(size_t)(d0 + y + i) * SEQ + s0 + x] = __float2half_rn(t[x][y + i]);
}

// ---------------------------------------------------------------------------
// Row softmax (len 2048, in place, fp32) + fp16 copy for GEMM2's A operand
// ---------------------------------------------------------------------------
__global__ __launch_bounds__(256)
void softmax_kernel(float* __restrict__ W, __half* __restrict__ Wh)
{
    const size_t row = blockIdx.x;
    float*  p  = W  + row * (size_t)SEQ;
    __half2* ph = reinterpret_cast<__half2*>(Wh + row * (size_t)SEQ);
    const int t = threadIdx.x;

    float4 v0 = reinterpret_cast<const float4*>(p)[t];
    float4 v1 = reinterpret_cast<const float4*>(p)[t + 256];

    float m = fmaxf(fmaxf(fmaxf(v0.x, v0.y), fmaxf(v0.z, v0.w)),
                    fmaxf(fmaxf(v1.x, v1.y), fmaxf(v1.z, v1.w)));

    __shared__ float red[8];
#pragma unroll
    for (int o = 16; o > 0; o >>= 1)
        m = fmaxf(m, __shfl_xor_sync(0xffffffffu, m, o));
    if ((t & 31) == 0) red[t >> 5] = m;
    __syncthreads();
    float rowmax = red[0];
#pragma unroll
    for (int i = 1; i < 8; i++) rowmax = fmaxf(rowmax, red[i]);
    __syncthreads();

    v0.x = __expf(v0.x - rowmax); v0.y = __expf(v0.y - rowmax);
    v0.z = __expf(v0.z - rowmax); v0.w = __expf(v0.w - rowmax);
    v1.x = __expf(v1.x - rowmax); v1.y = __expf(v1.y - rowmax);
    v1.z = __expf(v1.z - rowmax); v1.w = __expf(v1.w - rowmax);

    float s = ((v0.x + v0.y) + (v0.z + v0.w)) + ((v1.x + v1.y) + (v1.z + v1.w));
#pragma unroll
    for (int o = 16; o > 0; o >>= 1)
        s += __shfl_xor_sync(0xffffffffu, s, o);
    if ((t & 31) == 0) red[t >> 5] = s;
    __syncthreads();
    float rowsum = red[0];
#pragma unroll
    for (int i = 1; i < 8; i++) rowsum += red[i];

    const float inv = 1.0f / rowsum;
    v0.x *= inv; v0.y *= inv; v0.z *= inv; v0.w *= inv;
    v1.x *= inv; v1.y *= inv; v1.z *= inv; v1.w *= inv;

    reinterpret_cast<float4*>(p)[t]       = v0;
    reinterpret_cast<float4*>(p)[t + 256] = v1;

    ph[2 * t]           = __float22half2_rn(make_float2(v0.x, v0.y));
    ph[2 * t + 1]       = __float22half2_rn(make_float2(v0.z, v0.w));
    ph[512 + 2 * t]     = __float22half2_rn(make_float2(v1.x, v1.y));
    ph[512 + 2 * t + 1] = __float22half2_rn(make_float2(v1.z, v1.w));
}

// ---------------------------------------------------------------------------
// Launch: out = [output (B*S*D) | attention_weights (B*S*S)]
// ---------------------------------------------------------------------------
extern "C" void kernel_launch(void* const* d_in, const int* in_sizes, int n_in,
                              void* d_out, int out_size)
{
    (void)in_sizes; (void)n_in; (void)out_size;
    const float* q = (const float*)d_in[0];
    const float* k = (const float*)d_in[1];
    const float* v = (const float*)d_in[2];
    float* out = (float*)d_out;
    float* w   = out + (size_t)BATCH * SEQ * DIM;   // weights / scores region

    __half *qh, *kh, *vt, *wh;
    cudaGetSymbolAddress((void**)&qh, g_qh);
    cudaGetSymbolAddress((void**)&kh, g_kh);
    cudaGetSymbolAddress((void**)&vt, g_vt);
    cudaGetSymbolAddress((void**)&wh, g_wh);

    cudaFuncSetAttribute(gemm_h, cudaFuncAttributeMaxDynamicSharedMemorySize, HGEMM_DSMEM);

    const float inv_scale = 1.0f / sqrtf((float)SEQ);
    const int n4 = BATCH * SEQ * DIM / 4;

    // 1) convert Q, K to fp16
    to_half_kernel<<<(n4 + 255) / 256, 256>>>((const float4*)q, (__half2*)qh, n4);
    to_half_kernel<<<(n4 + 255) / 256, 256>>>((const float4*)k, (__half2*)kh, n4);

    // 2) transpose V -> Vt [B, D, S] fp16
    dim3 tg(SEQ / 32, DIM / 32, BATCH);
    transpose_half_kernel<<<tg, dim3(32, 8)>>>(v, vt);

    // 3) scores = Q K^T / sqrt(S)  (M=S, N=S, K=D)
    dim3 g1(SEQ / BN, SEQ / BM, BATCH);
    gemm_h<<<g1, 256, HGEMM_DSMEM>>>(qh, kh, w, SEQ, SEQ, DIM, inv_scale);

    // 4) softmax rows in place; fp16 copy to wh
    softmax_kernel<<<BATCH * SEQ, 256>>>(w, wh);

    // 5) out = W V  (M=S, N=D, K=S)
    dim3 g2(DIM / BN, SEQ / BM, BATCH);
    gemm_h<<<g2, 256, HGEMM_DSMEM>>>(wh, vt, out, SEQ, DIM, SEQ, 1.0f);
}